// round 1
// baseline (speedup 1.0000x reference)
#include <cuda_runtime.h>
#include <cuda_fp16.h>
#include <cuda_bf16.h>
#include <mma.h>

using namespace nvcuda;

#define BATCH      32
#define W_DIM      512
#define CHANNELS   1024
#define GRID_HW    64
#define HW         (GRID_HW * GRID_HW)      // 4096
#define TWO_PI     6.28318530717958647692f
#define GAIN       0.044194173824159216f    // 1/sqrt(512)
#define WSCALE     0.03125f                 // 1/sqrt(1024)

// ---------------- scratch (device globals; no runtime alloc allowed) --------
__device__ float  g_frx[BATCH * CHANNELS];
__device__ float  g_fry[BATCH * CHANNELS];
__device__ float  g_ph [BATCH * CHANNELS];
__device__ float  g_amp[BATCH * CHANNELS];

// separable trig tables: SA/CA depend on (b, w, c); SB/CB on (b, h, c)
__device__ float  g_SA[BATCH * GRID_HW * CHANNELS];
__device__ float  g_CA[BATCH * GRID_HW * CHANNELS];
__device__ float  g_SB[BATCH * GRID_HW * CHANNELS];
__device__ float  g_CB[BATCH * GRID_HW * CHANNELS];

// fp16 feature tensor F[b][m=h*64+w][c]  (268 MB)
__device__ __half g_F [(size_t)BATCH * HW * CHANNELS];
// fp16 weight (with 1/sqrt(C) folded in)
__device__ __half g_Wh[CHANNELS * CHANNELS];

// ---------------- stage 1: per-batch params ---------------------------------
__global__ void params_kernel(const float* __restrict__ w,
                              const float* __restrict__ affine_w,
                              const float* __restrict__ affine_b,
                              const float* __restrict__ freqs,
                              const float* __restrict__ phases) {
    __shared__ float t[BATCH][4];
    __shared__ float cs[BATCH], ss[BATCH], trx[BATCH], trY[BATCH];

    int tid = threadIdx.x;          // 128 threads
    int b = tid >> 2, j = tid & 3;  // (b, j) pair per thread

    float acc = 0.f;
    const float* wr = w + b * W_DIM;
    const float* ar = affine_w + j * W_DIM;
    #pragma unroll 4
    for (int k = 0; k < W_DIM; k++) acc += wr[k] * ar[k];
    t[b][j] = acc * GAIN + affine_b[j];
    __syncthreads();

    if (j == 0) {
        float t0 = t[b][0], t1 = t[b][1], t2 = t[b][2], t3 = t[b][3];
        float inv = rsqrtf(t0 * t0 + t1 * t1);
        float c = t0 * inv, s = t1 * inv, tx = t2 * inv, ty = t3 * inv;
        cs[b] = c; ss[b] = s;
        // trans = R @ (-tx,-ty) ; R = [[c,-s],[s,c]]
        trx[b] = -c * tx + s * ty;
        trY[b] = -s * tx - c * ty;
    }
    __syncthreads();

    for (int idx = tid; idx < BATCH * CHANNELS; idx += 128) {
        int bb = idx >> 10, c = idx & (CHANNELS - 1);
        float f0 = freqs[c * 2], f1 = freqs[c * 2 + 1];
        float C = cs[bb], S = ss[bb];
        // fr = freqs @ R
        float frx = f0 * C + f1 * S;
        float fry = -f0 * S + f1 * C;
        float ph  = phases[c] + f0 * trx[bb] + f1 * trY[bb];
        float nrm = sqrtf(frx * frx + fry * fry);
        float amp = 1.0f - (nrm - 2.0f) * (1.0f / 30.0f); // (SR/2 - BW) = 30
        amp = fminf(fmaxf(amp, 0.0f), 1.0f);
        g_frx[idx] = frx; g_fry[idx] = fry; g_ph[idx] = ph; g_amp[idx] = amp;
    }
}

// ---------------- stage 1b: weight -> fp16 -----------------------------------
__global__ void wconv_kernel(const float* __restrict__ weight) {
    int idx = blockIdx.x * blockDim.x + threadIdx.x;
    for (int i = idx; i < CHANNELS * CHANNELS; i += gridDim.x * blockDim.x)
        g_Wh[i] = __float2half(weight[i] * WSCALE);
}

// ---------------- stage 2: trig tables ---------------------------------------
__global__ void tables_kernel() {
    int b = blockIdx.x;
    int base = b * CHANNELS;
    for (int idx = threadIdx.x; idx < GRID_HW * CHANNELS; idx += blockDim.x) {
        int p = idx >> 10, c = idx & (CHANNELS - 1);
        float g = ((2 * p + 1) * (1.0f / GRID_HW) - 1.0f) * 0.5f; // gx == gy formula
        float frx = g_frx[base + c], fry = g_fry[base + c];
        float ph = g_ph[base + c], amp = g_amp[base + c];
        float sa, ca, sb, cb;
        __sincosf(0.0f, &sa, &ca); // placate nothing; replaced below
        sincosf(TWO_PI * g * frx, &sa, &ca);
        sincosf(TWO_PI * (g * fry + ph), &sb, &cb);
        int o = (b * GRID_HW + p) * CHANNELS + c;
        g_SA[o] = amp * sa;
        g_CA[o] = amp * ca;
        g_SB[o] = sb;
        g_CB[o] = cb;
    }
}

// ---------------- stage 3: feature tensor (fp16) -----------------------------
__global__ void features_kernel() {
    int h = blockIdx.x, b = blockIdx.y;
    __shared__ float sSB[CHANNELS], sCB[CHANNELS];
    int rowb = (b * GRID_HW + h) * CHANNELS;
    for (int c = threadIdx.x; c < CHANNELS; c += blockDim.x) {
        sSB[c] = g_SB[rowb + c];
        sCB[c] = g_CB[rowb + c];
    }
    __syncthreads();
    size_t fbase = ((size_t)b * HW + (size_t)h * GRID_HW) * CHANNELS;
    int abase = b * GRID_HW * CHANNELS;
    for (int idx = threadIdx.x; idx < GRID_HW * CHANNELS; idx += blockDim.x) {
        int w2 = idx >> 10, c = idx & (CHANNELS - 1);
        float sa = g_SA[abase + w2 * CHANNELS + c];
        float ca = g_CA[abase + w2 * CHANNELS + c];
        float v = sa * sCB[c] + ca * sSB[c];
        g_F[fbase + (size_t)w2 * CHANNELS + c] = __float2half(v);
    }
}

// ---------------- stage 4: batched GEMM (wmma fp16, fp32 accum) --------------
// out[b][o][m] = sum_c F[b][m][c] * Wh[o][c] ,  m = h*64+w
#define BM 128
#define BN 128
#define BK 32
#define LDS 40   // padded smem leading dim (multiple of 8)

__global__ void __launch_bounds__(256, 1)
gemm_kernel(float* __restrict__ out) {
    __shared__ __half As[BM * LDS];
    __shared__ __half Bs[BN * LDS];

    int b  = blockIdx.z;
    int mt = blockIdx.y;
    int nt = blockIdx.x;

    const __half* A = g_F + (size_t)b * HW * CHANNELS + (size_t)mt * BM * CHANNELS;
    const __half* B = g_Wh + (size_t)nt * BN * CHANNELS;

    int tid = threadIdx.x;
    int wid = tid >> 5;
    int wm = wid >> 2;      // 0..1  -> 64-row M slab
    int wn = wid & 3;       // 0..3  -> 32-col N slab

    wmma::fragment<wmma::accumulator, 16, 16, 16, float> acc[4][2];
    #pragma unroll
    for (int i = 0; i < 4; i++)
        #pragma unroll
        for (int j = 0; j < 2; j++)
            wmma::fill_fragment(acc[i][j], 0.0f);

    for (int k0 = 0; k0 < CHANNELS; k0 += BK) {
        // stage tiles: 128x32 halves each = 512 uint4; 2 per thread per tile
        #pragma unroll
        for (int r = 0; r < 2; r++) {
            int u   = tid + r * 256;
            int row = u >> 2;
            int cg  = (u & 3) * 8;
            *(uint4*)&As[row * LDS + cg] =
                *(const uint4*)&A[(size_t)row * CHANNELS + k0 + cg];
            *(uint4*)&Bs[row * LDS + cg] =
                *(const uint4*)&B[(size_t)row * CHANNELS + k0 + cg];
        }
        __syncthreads();

        #pragma unroll
        for (int kk = 0; kk < BK; kk += 16) {
            wmma::fragment<wmma::matrix_a, 16, 16, 16, __half, wmma::row_major> af[4];
            wmma::fragment<wmma::matrix_b, 16, 16, 16, __half, wmma::col_major> bf[2];
            #pragma unroll
            for (int i = 0; i < 4; i++)
                wmma::load_matrix_sync(af[i], &As[(wm * 64 + i * 16) * LDS + kk], LDS);
            #pragma unroll
            for (int j = 0; j < 2; j++)
                wmma::load_matrix_sync(bf[j], &Bs[(wn * 32 + j * 16) * LDS + kk], LDS);
            #pragma unroll
            for (int i = 0; i < 4; i++)
                #pragma unroll
                for (int j = 0; j < 2; j++)
                    wmma::mma_sync(acc[i][j], af[i], bf[j], acc[i][j]);
        }
        __syncthreads();
    }

    // epilogue: out is [b][o][m]; store C(m,n) transposed via col-major store
    float* outB = out + (size_t)b * CHANNELS * HW;
    #pragma unroll
    for (int i = 0; i < 4; i++) {
        #pragma unroll
        for (int j = 0; j < 2; j++) {
            int m = mt * BM + wm * 64 + i * 16;
            int n = nt * BN + wn * 32 + j * 16;
            wmma::store_matrix_sync(outB + (size_t)n * HW + m, acc[i][j],
                                    HW, wmma::mem_col_major);
        }
    }
}

// ---------------- launch ------------------------------------------------------
extern "C" void kernel_launch(void* const* d_in, const int* in_sizes, int n_in,
                              void* d_out, int out_size) {
    const float* w        = (const float*)d_in[0];
    const float* affine_w = (const float*)d_in[1];
    const float* affine_b = (const float*)d_in[2];
    const float* freqs    = (const float*)d_in[3];
    const float* phases   = (const float*)d_in[4];
    const float* weight   = (const float*)d_in[5];
    float* out = (float*)d_out;

    params_kernel<<<1, 128>>>(w, affine_w, affine_b, freqs, phases);
    wconv_kernel<<<512, 256>>>(weight);
    tables_kernel<<<BATCH, 256>>>();
    features_kernel<<<dim3(GRID_HW, BATCH), 256>>>();
    gemm_kernel<<<dim3(CHANNELS / BN, HW / BM, BATCH), 256>>>(out);
}

// round 3
// speedup vs baseline: 1.5827x; 1.5827x over previous
#include <cuda_runtime.h>
#include <cuda_fp16.h>
#include <cuda_bf16.h>
#include <cstdint>

#define BATCH      32
#define W_DIM      512
#define CHANNELS   1024
#define GRID_HW    64
#define HW         (GRID_HW * GRID_HW)      // 4096
#define TWO_PI     6.28318530717958647692f
#define GAIN       0.044194173824159216f    // 1/sqrt(512)
#define WSCALE     0.03125f                 // 1/sqrt(1024)

// ---------------- scratch (device globals; no runtime alloc) -----------------
__device__ float  g_frx[BATCH * CHANNELS];
__device__ float  g_fry[BATCH * CHANNELS];
__device__ float  g_ph [BATCH * CHANNELS];
__device__ float  g_amp[BATCH * CHANNELS];

// fp16 separable trig tables, c fastest: [b][p][c]
__device__ __half g_SAh[BATCH * GRID_HW * CHANNELS];  // amp*sin(2pi g frx)
__device__ __half g_CAh[BATCH * GRID_HW * CHANNELS];  // amp*cos(2pi g frx)
__device__ __half g_SBh[BATCH * GRID_HW * CHANNELS];  // sin(2pi (g fry + ph))
__device__ __half g_CBh[BATCH * GRID_HW * CHANNELS];  // cos(2pi (g fry + ph))

// fp16 weight (1/sqrt(C) folded), row-major [o][c]
__device__ __half g_Wh[CHANNELS * CHANNELS];

// ---------------- PTX helpers -----------------------------------------------
__device__ __forceinline__ uint32_t smem_u32(const void* p) {
    uint32_t a;
    asm("{ .reg .u64 t; cvta.to.shared.u64 t, %1; cvt.u32.u64 %0, t; }"
        : "=r"(a) : "l"(p));
    return a;
}

__device__ __forceinline__ void ldsm4(uint32_t* r, uint32_t addr) {
    asm volatile("ldmatrix.sync.aligned.m8n8.x4.shared.b16 {%0,%1,%2,%3}, [%4];"
                 : "=r"(r[0]), "=r"(r[1]), "=r"(r[2]), "=r"(r[3]) : "r"(addr));
}

__device__ __forceinline__ void mma16816(float* d, const uint32_t* a,
                                         const uint32_t* b) {
    asm volatile(
        "mma.sync.aligned.m16n8k16.row.col.f32.f16.f16.f32 "
        "{%0,%1,%2,%3}, {%4,%5,%6,%7}, {%8,%9}, {%0,%1,%2,%3};"
        : "+f"(d[0]), "+f"(d[1]), "+f"(d[2]), "+f"(d[3])
        : "r"(a[0]), "r"(a[1]), "r"(a[2]), "r"(a[3]), "r"(b[0]), "r"(b[1]));
}

__device__ __forceinline__ void cp16(uint32_t dst, const void* src) {
    asm volatile("cp.async.ca.shared.global [%0], [%1], 16;"
                 :: "r"(dst), "l"(src));
}
#define CP_COMMIT() asm volatile("cp.async.commit_group;" ::: "memory")
#define CP_WAIT0()  asm volatile("cp.async.wait_group 0;"  ::: "memory")

// ---------------- stage 1: per-batch params ----------------------------------
__global__ void params_kernel(const float* __restrict__ w,
                              const float* __restrict__ affine_w,
                              const float* __restrict__ affine_b,
                              const float* __restrict__ freqs,
                              const float* __restrict__ phases) {
    __shared__ float t[BATCH][4];
    __shared__ float cs[BATCH], ss[BATCH], trx[BATCH], trY[BATCH];

    int tid = threadIdx.x;          // 128 threads
    int b = tid >> 2, j = tid & 3;

    float acc = 0.f;
    const float* wr = w + b * W_DIM;
    const float* ar = affine_w + j * W_DIM;
    #pragma unroll 4
    for (int k = 0; k < W_DIM; k++) acc += wr[k] * ar[k];
    t[b][j] = acc * GAIN + affine_b[j];
    __syncthreads();

    if (j == 0) {
        float t0 = t[b][0], t1 = t[b][1], t2 = t[b][2], t3 = t[b][3];
        float inv = rsqrtf(t0 * t0 + t1 * t1);
        float c = t0 * inv, s = t1 * inv, tx = t2 * inv, ty = t3 * inv;
        cs[b] = c; ss[b] = s;
        trx[b] = -c * tx + s * ty;
        trY[b] = -s * tx - c * ty;
    }
    __syncthreads();

    for (int idx = tid; idx < BATCH * CHANNELS; idx += 128) {
        int bb = idx >> 10, c = idx & (CHANNELS - 1);
        float f0 = freqs[c * 2], f1 = freqs[c * 2 + 1];
        float C = cs[bb], S = ss[bb];
        float frx = f0 * C + f1 * S;
        float fry = -f0 * S + f1 * C;
        float ph  = phases[c] + f0 * trx[bb] + f1 * trY[bb];
        float nrm = sqrtf(frx * frx + fry * fry);
        float amp = 1.0f - (nrm - 2.0f) * (1.0f / 30.0f);
        amp = fminf(fmaxf(amp, 0.0f), 1.0f);
        g_frx[idx] = frx; g_fry[idx] = fry; g_ph[idx] = ph; g_amp[idx] = amp;
    }
}

// ---------------- stage 1b: weight -> fp16 -----------------------------------
__global__ void wconv_kernel(const float* __restrict__ weight) {
    int idx = blockIdx.x * blockDim.x + threadIdx.x;
    for (int i = idx; i < CHANNELS * CHANNELS; i += gridDim.x * blockDim.x)
        g_Wh[i] = __float2half(weight[i] * WSCALE);
}

// ---------------- stage 2: fp16 trig tables ----------------------------------
__global__ void tables_kernel() {
    int p = blockIdx.x, b = blockIdx.y;
    int base = b * CHANNELS;
    float g = ((2 * p + 1) * (1.0f / GRID_HW) - 1.0f) * 0.5f;
    int o = (b * GRID_HW + p) * CHANNELS;
    for (int c = threadIdx.x; c < CHANNELS; c += blockDim.x) {
        float frx = g_frx[base + c], fry = g_fry[base + c];
        float ph = g_ph[base + c], amp = g_amp[base + c];
        float sa, ca, sb, cb;
        sincosf(TWO_PI * g * frx, &sa, &ca);
        sincosf(TWO_PI * (g * fry + ph), &sb, &cb);
        g_SAh[o + c] = __float2half(amp * sa);
        g_CAh[o + c] = __float2half(amp * ca);
        g_SBh[o + c] = __float2half(sb);
        g_CBh[o + c] = __float2half(cb);
    }
}

// ---------------- stage 3: fused mma.sync GEMM -------------------------------
// Per CTA: D[o=128, px=128] for (ot, pt, b).  px tile = 2 h-rows x 64 w.
// B tile (128 px x 32 c fp16) generated in SMEM from trig tables; A tile
// (128 o x 32 c) cp.async'd from g_Wh. K=1024 in 32 iters of 32.
#define BK      32
#define STRIDE  40                    // halves, padded (conflict-free ldsm)
#define ABUF    (128 * STRIDE * 2)    // 10240 B per buffer

__global__ void __launch_bounds__(128, 2)
gemm_mma(float* __restrict__ out) {
    __shared__ __half sA[2][128 * STRIDE];
    __shared__ __half sB[2][128 * STRIDE];

    int tid = threadIdx.x;
    int ot = blockIdx.x;   // 8
    int pt = blockIdx.y;   // 32
    int b  = blockIdx.z;   // 32

    uint32_t sAu = smem_u32(sA);
    uint32_t sBu = smem_u32(sB);

    // ---- B generation setup: thread -> (w = tid&63, c16 group) --------------
    int w  = tid & 63;
    int c16 = ((tid >> 6) & 1) * 16;
    size_t tb = (size_t)b * GRID_HW;
    const __half* SAp = g_SAh + ((tb + w) << 10);
    const __half* CAp = g_CAh + ((tb + w) << 10);
    const __half* SB0 = g_SBh + ((tb + pt * 2) << 10);
    const __half* CB0 = g_CBh + ((tb + pt * 2) << 10);
    const __half* SB1 = SB0 + CHANNELS;
    const __half* CB1 = CB0 + CHANNELS;

    // ---- A cp.async setup ---------------------------------------------------
    int ar = tid >> 2;                 // base row (o within tile)
    int ac = (tid & 3) * 8;            // c offset (halves)
    const __half* wsrc0 = g_Wh + (size_t)(ot * 128 + ar) * CHANNELS + ac;
    uint32_t adst0 = (uint32_t)(ar * STRIDE + ac) * 2;

    // ---- mma lane geometry --------------------------------------------------
    int wid = tid >> 5, lane = tid & 31;
    int m0 = (wid >> 1) * 64, n0 = (wid & 1) * 64;
    int la = lane & 7, lb = (lane >> 3) & 1, lc = lane >> 4;
    uint32_t aRow = (uint32_t)((m0 + la + lb * 8) * STRIDE + lc * 8) * 2;
    uint32_t bRow = (uint32_t)((n0 + la + lc * 8) * STRIDE + lb * 8) * 2;

    float acc[4][8][4];
    #pragma unroll
    for (int i = 0; i < 4; i++)
        #pragma unroll
        for (int j = 0; j < 8; j++)
            #pragma unroll
            for (int q = 0; q < 4; q++) acc[i][j][q] = 0.f;

    // ---- helpers (inlined via lambdas) --------------------------------------
    auto cpasyncA = [&](int k, int buf) {
        const __half* ws = wsrc0 + k * BK;
        uint32_t ad = sAu + buf * ABUF + adst0;
        #pragma unroll
        for (int j = 0; j < 4; j++)
            cp16(ad + j * 32 * STRIDE * 2, ws + (size_t)j * 32 * CHANNELS);
    };

    auto genB = [&](int k, int buf) {
        int off = k * BK + c16;
        uint4 xsa0 = *(const uint4*)(SAp + off);
        uint4 xsa1 = *(const uint4*)(SAp + off + 8);
        uint4 xca0 = *(const uint4*)(CAp + off);
        uint4 xca1 = *(const uint4*)(CAp + off + 8);
        uint4 s00  = *(const uint4*)(SB0 + off);
        uint4 s01  = *(const uint4*)(SB0 + off + 8);
        uint4 c00  = *(const uint4*)(CB0 + off);
        uint4 c01  = *(const uint4*)(CB0 + off + 8);
        uint4 s10  = *(const uint4*)(SB1 + off);
        uint4 s11  = *(const uint4*)(SB1 + off + 8);
        uint4 c10  = *(const uint4*)(CB1 + off);
        uint4 c11  = *(const uint4*)(CB1 + off + 8);
        uint4 o00, o01, o10, o11;
        const __half2* sa0 = (const __half2*)&xsa0;
        const __half2* sa1 = (const __half2*)&xsa1;
        const __half2* ca0 = (const __half2*)&xca0;
        const __half2* ca1 = (const __half2*)&xca1;
        #pragma unroll
        for (int j = 0; j < 4; j++) {
            ((__half2*)&o00)[j] = __hfma2(sa0[j], ((const __half2*)&c00)[j],
                                  __hmul2(ca0[j], ((const __half2*)&s00)[j]));
            ((__half2*)&o01)[j] = __hfma2(sa1[j], ((const __half2*)&c01)[j],
                                  __hmul2(ca1[j], ((const __half2*)&s01)[j]));
            ((__half2*)&o10)[j] = __hfma2(sa0[j], ((const __half2*)&c10)[j],
                                  __hmul2(ca0[j], ((const __half2*)&s10)[j]));
            ((__half2*)&o11)[j] = __hfma2(sa1[j], ((const __half2*)&c11)[j],
                                  __hmul2(ca1[j], ((const __half2*)&s11)[j]));
        }
        __half* d0 = &sB[buf][w * STRIDE + c16];          // h=0 -> px=w
        __half* d1 = &sB[buf][(64 + w) * STRIDE + c16];   // h=1 -> px=64+w
        *(uint4*)d0 = o00; *(uint4*)(d0 + 8) = o01;
        *(uint4*)d1 = o10; *(uint4*)(d1 + 8) = o11;
    };

    // ---- prologue -----------------------------------------------------------
    cpasyncA(0, 0); CP_COMMIT();
    genB(0, 0);
    CP_WAIT0();
    __syncthreads();

    // ---- main loop ----------------------------------------------------------
    for (int k = 0; k < CHANNELS / BK; k++) {
        int cur = k & 1;
        if (k < CHANNELS / BK - 1) {
            cpasyncA(k + 1, cur ^ 1); CP_COMMIT();
            genB(k + 1, cur ^ 1);
        }

        uint32_t abase = sAu + cur * ABUF + aRow;
        uint32_t bbase = sBu + cur * ABUF + bRow;
        #pragma unroll
        for (int ks = 0; ks < 2; ks++) {
            uint32_t af[4][4], bf[4][4];
            #pragma unroll
            for (int im = 0; im < 4; im++)
                ldsm4(af[im], abase + im * 16 * STRIDE * 2 + ks * 32);
            #pragma unroll
            for (int ib = 0; ib < 4; ib++)
                ldsm4(bf[ib], bbase + ib * 16 * STRIDE * 2 + ks * 32);
            #pragma unroll
            for (int im = 0; im < 4; im++)
                #pragma unroll
                for (int ib = 0; ib < 4; ib++) {
                    mma16816(acc[im][2 * ib],     af[im], &bf[ib][0]);
                    mma16816(acc[im][2 * ib + 1], af[im], &bf[ib][2]);
                }
        }

        if (k < CHANNELS / BK - 1) CP_WAIT0();
        __syncthreads();
    }

    // ---- epilogue: direct STG.64, 32B-sector coalesced ----------------------
    #pragma unroll
    for (int im = 0; im < 4; im++) {
        int o = ot * 128 + m0 + im * 16 + (lane >> 2);
        float* p = out + ((size_t)(b * CHANNELS + o)) * HW
                       + (size_t)pt * 128 + n0 + 2 * (lane & 3);
        #pragma unroll
        for (int inf = 0; inf < 8; inf++) {
            float2 vlo = make_float2(acc[im][inf][0], acc[im][inf][1]);
            float2 vhi = make_float2(acc[im][inf][2], acc[im][inf][3]);
            *(float2*)(p + inf * 8)            = vlo;   // row o
            *(float2*)(p + inf * 8 + 8 * HW)   = vhi;   // row o+8
        }
    }
}

// ---------------- launch ------------------------------------------------------
extern "C" void kernel_launch(void* const* d_in, const int* in_sizes, int n_in,
                              void* d_out, int out_size) {
    const float* w        = (const float*)d_in[0];
    const float* affine_w = (const float*)d_in[1];
    const float* affine_b = (const float*)d_in[2];
    const float* freqs    = (const float*)d_in[3];
    const float* phases   = (const float*)d_in[4];
    const float* weight   = (const float*)d_in[5];
    float* out = (float*)d_out;

    params_kernel<<<1, 128>>>(w, affine_w, affine_b, freqs, phases);
    wconv_kernel<<<512, 256>>>(weight);
    tables_kernel<<<dim3(GRID_HW, BATCH), 256>>>();
    gemm_mma<<<dim3(8, 32, BATCH), 128>>>(out);
}

// round 4
// speedup vs baseline: 2.0256x; 1.2798x over previous
#include <cuda_runtime.h>
#include <cuda_fp16.h>
#include <cuda_bf16.h>
#include <cstdint>

#define BATCH      32
#define W_DIM      512
#define CHANNELS   1024
#define GRID_HW    64
#define HW         (GRID_HW * GRID_HW)      // 4096
#define TWO_PI     6.28318530717958647692f
#define GAIN       0.044194173824159216f    // 1/sqrt(512)
#define WSCALE     0.03125f                 // 1/sqrt(1024)

// ---------------- scratch (device globals; no runtime alloc) -----------------
__device__ float  g_frx[BATCH * CHANNELS];
__device__ float  g_fry[BATCH * CHANNELS];
__device__ float  g_ph [BATCH * CHANNELS];
__device__ float  g_amp[BATCH * CHANNELS];

// fp16 trig tables, p (w or h) FASTEST: [b][c][p]  (contiguous K-chunk blocks)
__device__ __half g_SAt[BATCH * CHANNELS * GRID_HW];  // amp*sin(2pi g(w) frx)
__device__ __half g_CAt[BATCH * CHANNELS * GRID_HW];  // amp*cos(2pi g(w) frx)
__device__ __half g_SBt[BATCH * CHANNELS * GRID_HW];  // sin(2pi (g(h) fry + ph))
__device__ __half g_CBt[BATCH * CHANNELS * GRID_HW];  // cos(2pi (g(h) fry + ph))

// fp16 weight (1/sqrt(C) folded), row-major [o][c]
__device__ __half g_Wh[CHANNELS * CHANNELS];

// ---------------- PTX helpers -----------------------------------------------
__device__ __forceinline__ uint32_t smem_u32(const void* p) {
    uint32_t a;
    asm("{ .reg .u64 t; cvta.to.shared.u64 t, %1; cvt.u32.u64 %0, t; }"
        : "=r"(a) : "l"(p));
    return a;
}

__device__ __forceinline__ void ldsm4(uint32_t* r, uint32_t addr) {
    asm volatile("ldmatrix.sync.aligned.m8n8.x4.shared.b16 {%0,%1,%2,%3}, [%4];"
                 : "=r"(r[0]), "=r"(r[1]), "=r"(r[2]), "=r"(r[3]) : "r"(addr));
}
__device__ __forceinline__ void ldsm4t(uint32_t* r, uint32_t addr) {
    asm volatile("ldmatrix.sync.aligned.m8n8.x4.trans.shared.b16 {%0,%1,%2,%3}, [%4];"
                 : "=r"(r[0]), "=r"(r[1]), "=r"(r[2]), "=r"(r[3]) : "r"(addr));
}

__device__ __forceinline__ void mma16816(float* d, const uint32_t* a,
                                         const uint32_t* b) {
    asm volatile(
        "mma.sync.aligned.m16n8k16.row.col.f32.f16.f16.f32 "
        "{%0,%1,%2,%3}, {%4,%5,%6,%7}, {%8,%9}, {%0,%1,%2,%3};"
        : "+f"(d[0]), "+f"(d[1]), "+f"(d[2]), "+f"(d[3])
        : "r"(a[0]), "r"(a[1]), "r"(a[2]), "r"(a[3]), "r"(b[0]), "r"(b[1]));
}

__device__ __forceinline__ void cp16(uint32_t dst, const void* src) {
    asm volatile("cp.async.ca.shared.global [%0], [%1], 16;"
                 :: "r"(dst), "l"(src));
}
__device__ __forceinline__ void cp4(uint32_t dst, const void* src) {
    asm volatile("cp.async.ca.shared.global [%0], [%1], 4;"
                 :: "r"(dst), "l"(src));
}
#define CP_COMMIT() asm volatile("cp.async.commit_group;" ::: "memory")
#define CP_WAIT0()  asm volatile("cp.async.wait_group 0;"  ::: "memory")

// ---------------- stage 1: per-batch params ----------------------------------
__global__ void params_kernel(const float* __restrict__ w,
                              const float* __restrict__ affine_w,
                              const float* __restrict__ affine_b,
                              const float* __restrict__ freqs,
                              const float* __restrict__ phases) {
    __shared__ float t[BATCH][4];
    __shared__ float cs[BATCH], ss[BATCH], trx[BATCH], trY[BATCH];

    int tid = threadIdx.x;          // 128 threads
    int b = tid >> 2, j = tid & 3;

    float acc = 0.f;
    const float* wr = w + b * W_DIM;
    const float* ar = affine_w + j * W_DIM;
    #pragma unroll 4
    for (int k = 0; k < W_DIM; k++) acc += wr[k] * ar[k];
    t[b][j] = acc * GAIN + affine_b[j];
    __syncthreads();

    if (j == 0) {
        float t0 = t[b][0], t1 = t[b][1], t2 = t[b][2], t3 = t[b][3];
        float inv = rsqrtf(t0 * t0 + t1 * t1);
        float c = t0 * inv, s = t1 * inv, tx = t2 * inv, ty = t3 * inv;
        cs[b] = c; ss[b] = s;
        trx[b] = -c * tx + s * ty;
        trY[b] = -s * tx - c * ty;
    }
    __syncthreads();

    for (int idx = tid; idx < BATCH * CHANNELS; idx += 128) {
        int bb = idx >> 10, c = idx & (CHANNELS - 1);
        float f0 = freqs[c * 2], f1 = freqs[c * 2 + 1];
        float C = cs[bb], S = ss[bb];
        float frx = f0 * C + f1 * S;
        float fry = -f0 * S + f1 * C;
        float ph  = phases[c] + f0 * trx[bb] + f1 * trY[bb];
        float nrm = sqrtf(frx * frx + fry * fry);
        float amp = 1.0f - (nrm - 2.0f) * (1.0f / 30.0f);
        amp = fminf(fmaxf(amp, 0.0f), 1.0f);
        g_frx[idx] = frx; g_fry[idx] = fry; g_ph[idx] = ph; g_amp[idx] = amp;
    }
}

// ---------------- stage 1b: weight -> fp16 -----------------------------------
__global__ void wconv_kernel(const float* __restrict__ weight) {
    int idx = blockIdx.x * blockDim.x + threadIdx.x;
    for (int i = idx; i < CHANNELS * CHANNELS; i += gridDim.x * blockDim.x)
        g_Wh[i] = __float2half(weight[i] * WSCALE);
}

// ---------------- stage 2: fp16 trig tables (p-fastest) ----------------------
__global__ void tables_kernel() {
    int tid = threadIdx.x;                       // 256
    int c = blockIdx.x * 4 + (tid >> 6);
    int p = tid & 63;
    int b = blockIdx.y;
    int pi = b * CHANNELS + c;
    float g = ((2 * p + 1) * (1.0f / GRID_HW) - 1.0f) * 0.5f;
    float frx = g_frx[pi], fry = g_fry[pi];
    float ph = g_ph[pi], amp = g_amp[pi];
    float sa, ca, sb, cb;
    sincosf(TWO_PI * g * frx, &sa, &ca);
    sincosf(TWO_PI * (g * fry + ph), &sb, &cb);
    int o = pi * GRID_HW + p;
    g_SAt[o] = __float2half(amp * sa);
    g_CAt[o] = __float2half(amp * ca);
    g_SBt[o] = __float2half(sb);
    g_CBt[o] = __float2half(cb);
}

// ---------------- stage 3: fused mma.sync GEMM -------------------------------
// CTA tile: M=256 (o) x N=128 (px), K=1024 in 32 iters of BK=32.
// B tile (32c x 128px, k-major) generated in SMEM from staged trig tables.
#define BK       32
#define ASTRIDE  40      // halves
#define BSTRIDE  136     // halves (128 px + 8 pad)
#define TSTRIDE  72      // halves (64 p + 8 pad)

// half-offsets within dynamic smem
#define OFF_A    0                         // 2 * 256*40  = 20480
#define OFF_B    20480                     // 2 * 32*136  = 8704
#define OFF_T    29184                     // 2 * 4736    = 9472
#define T_CA     2304
#define T_SB     4608
#define T_CB     4672
#define TBUF     4736
#define SMEM_BYTES ((29184 + 2 * 4736) * 2)   // 77312

__global__ void __launch_bounds__(256, 1)
gemm_mma(float* __restrict__ out) {
    extern __shared__ __half sh[];
    int tid = threadIdx.x;
    int ot = blockIdx.x;   // 4
    int pt = blockIdx.y;   // 32
    int b  = blockIdx.z;   // 32

    uint32_t sAu = smem_u32(sh + OFF_A);
    uint32_t sBu = smem_u32(sh + OFF_B);
    uint32_t sTu = smem_u32(sh + OFF_T);
    int h0 = pt * 2;

    // ---- cp.async staging ---------------------------------------------------
    // A: rows grouped 4-lanes-per-row for full-sector coalescing
    int arow = tid >> 2, aseg = tid & 3;
    const __half* wsrc0 = g_Wh + (size_t)(ot * 256 + arow) * CHANNELS + aseg * 8;
    // tables: 8-lanes-per-row (rows contiguous 128B in gmem)
    int trow = tid >> 3, tseg = tid & 7;

    auto stage = [&](int k, int buf) {
        int ck = k * BK;
        // A (256 x 32 halves)
        uint32_t ad = sAu + (uint32_t)(buf * 10240 + arow * ASTRIDE + aseg * 8) * 2;
        const __half* ws = wsrc0 + ck;
        #pragma unroll
        for (int j = 0; j < 4; j++)
            cp16(ad + (uint32_t)(j * 64 * ASTRIDE) * 2, ws + (size_t)j * 64 * CHANNELS);
        // SA / CA chunks (32c x 64p, contiguous 4KB each)
        const __half* sasrc = g_SAt + ((size_t)(b * CHANNELS + ck + trow) << 6) + tseg * 8;
        const __half* casrc = g_CAt + ((size_t)(b * CHANNELS + ck + trow) << 6) + tseg * 8;
        uint32_t td = sTu + (uint32_t)(buf * TBUF + trow * TSTRIDE + tseg * 8) * 2;
        cp16(td, sasrc);
        cp16(td + T_CA * 2, casrc);
        // SB / CB (32c x 2h)
        if (tid < 32) {
            const __half* s = g_SBt + ((size_t)(b * CHANNELS + ck + tid) << 6) + h0;
            cp4(sTu + (uint32_t)(buf * TBUF + T_SB + tid * 2) * 2, s);
        } else if (tid < 64) {
            int c = tid - 32;
            const __half* s = g_CBt + ((size_t)(b * CHANNELS + ck + c) << 6) + h0;
            cp4(sTu + (uint32_t)(buf * TBUF + T_CB + c * 2) * 2, s);
        }
    };

    // ---- B generation from staged tables ------------------------------------
    int gc = tid >> 3;            // c row 0..31
    int gj = tid & 7;             // px-16 group
    int gpx = gj * 16;
    int gh = gpx >> 6;            // 0..1
    int gw = gpx & 63;

    auto genB = [&](int buf) {
        const __half* T = sh + OFF_T + buf * TBUF;
        uint4 xsa0 = *(const uint4*)(T + gc * TSTRIDE + gw);
        uint4 xsa1 = *(const uint4*)(T + gc * TSTRIDE + gw + 8);
        uint4 xca0 = *(const uint4*)(T + T_CA + gc * TSTRIDE + gw);
        uint4 xca1 = *(const uint4*)(T + T_CA + gc * TSTRIDE + gw + 8);
        __half sbv = T[T_SB + gc * 2 + gh];
        __half cbv = T[T_CB + gc * 2 + gh];
        __half2 sb2 = __half2half2(sbv), cb2 = __half2half2(cbv);
        uint4 o0, o1;
        #pragma unroll
        for (int j = 0; j < 4; j++) {
            ((__half2*)&o0)[j] = __hfma2(((const __half2*)&xsa0)[j], cb2,
                                 __hmul2(((const __half2*)&xca0)[j], sb2));
            ((__half2*)&o1)[j] = __hfma2(((const __half2*)&xsa1)[j], cb2,
                                 __hmul2(((const __half2*)&xca1)[j], sb2));
        }
        __half* d = sh + OFF_B + buf * 4352 + gc * BSTRIDE + gpx;
        *(uint4*)d = o0;
        *(uint4*)(d + 8) = o1;
    };

    // ---- mma geometry -------------------------------------------------------
    int wid = tid >> 5, lane = tid & 31;
    int m0 = (wid >> 1) * 64;     // 0..192
    int n0 = (wid & 1) * 64;      // 0 / 64
    uint32_t aAddr0 = sAu + (uint32_t)((m0 + (lane & 15)) * ASTRIDE + (lane >> 4) * 8) * 2;
    uint32_t bAddr0 = sBu + (uint32_t)((lane & 15) * BSTRIDE + n0 + (lane >> 4) * 8) * 2;

    float acc[4][8][4];
    #pragma unroll
    for (int i = 0; i < 4; i++)
        #pragma unroll
        for (int j = 0; j < 8; j++)
            #pragma unroll
            for (int q = 0; q < 4; q++) acc[i][j][q] = 0.f;

    // ---- prologue -----------------------------------------------------------
    stage(0, 0); CP_COMMIT();
    CP_WAIT0(); __syncthreads();
    genB(0);
    __syncthreads();

    // ---- main loop ----------------------------------------------------------
    #define NKIT (CHANNELS / BK)
    for (int k = 0; k < NKIT; k++) {
        int cur = k & 1, nxt = cur ^ 1;
        if (k < NKIT - 1) { stage(k + 1, nxt); CP_COMMIT(); }

        uint32_t aA = aAddr0 + (uint32_t)(cur * 10240) * 2;
        uint32_t bA = bAddr0 + (uint32_t)(cur * 4352) * 2;
        #pragma unroll
        for (int ks = 0; ks < 2; ks++) {
            uint32_t af[4][4], bf[4][4];
            #pragma unroll
            for (int im = 0; im < 4; im++)
                ldsm4(af[im], aA + (uint32_t)(im * 16 * ASTRIDE) * 2 + ks * 32);
            #pragma unroll
            for (int in = 0; in < 4; in++)
                ldsm4t(bf[in], bA + (uint32_t)(ks * 16 * BSTRIDE) * 2 + in * 32);
            #pragma unroll
            for (int im = 0; im < 4; im++)
                #pragma unroll
                for (int in = 0; in < 4; in++) {
                    mma16816(acc[im][2 * in],     af[im], &bf[in][0]);
                    mma16816(acc[im][2 * in + 1], af[im], &bf[in][2]);
                }
        }

        if (k < NKIT - 1) {
            CP_WAIT0();
            __syncthreads();
            genB(nxt);
        }
        __syncthreads();
    }

    // ---- epilogue: direct STG, 32B-sector coalesced -------------------------
    #pragma unroll
    for (int im = 0; im < 4; im++) {
        int o = ot * 256 + m0 + im * 16 + (lane >> 2);
        float* p = out + ((size_t)(b * CHANNELS + o)) * HW
                       + (size_t)pt * 128 + n0 + 2 * (lane & 3);
        #pragma unroll
        for (int inf = 0; inf < 8; inf++) {
            float2 vlo = make_float2(acc[im][inf][0], acc[im][inf][1]);
            float2 vhi = make_float2(acc[im][inf][2], acc[im][inf][3]);
            *(float2*)(p + inf * 8)          = vlo;   // row o
            *(float2*)(p + inf * 8 + 8 * HW) = vhi;   // row o+8
        }
    }
}

// ---------------- launch ------------------------------------------------------
extern "C" void kernel_launch(void* const* d_in, const int* in_sizes, int n_in,
                              void* d_out, int out_size) {
    const float* w        = (const float*)d_in[0];
    const float* affine_w = (const float*)d_in[1];
    const float* affine_b = (const float*)d_in[2];
    const float* freqs    = (const float*)d_in[3];
    const float* phases   = (const float*)d_in[4];
    const float* weight   = (const float*)d_in[5];
    float* out = (float*)d_out;

    cudaFuncSetAttribute(gemm_mma, cudaFuncAttributeMaxDynamicSharedMemorySize,
                         SMEM_BYTES);

    params_kernel<<<1, 128>>>(w, affine_w, affine_b, freqs, phases);
    wconv_kernel<<<512, 256>>>(weight);
    tables_kernel<<<dim3(CHANNELS / 4, BATCH), 256>>>();
    gemm_mma<<<dim3(4, 32, BATCH), 256, SMEM_BYTES>>>(out);
}

// round 5
// speedup vs baseline: 2.1861x; 1.0793x over previous
#include <cuda_runtime.h>
#include <cuda_fp16.h>
#include <cuda_bf16.h>
#include <cstdint>

#define BATCH      32
#define W_DIM      512
#define CHANNELS   1024
#define GRID_HW    64
#define HW         (GRID_HW * GRID_HW)      // 4096
#define TWO_PI     6.28318530717958647692f
#define GAIN       0.044194173824159216f    // 1/sqrt(512)
#define WSCALE     0.03125f                 // 1/sqrt(1024)

// ---------------- scratch (device globals; no runtime alloc) -----------------
__device__ float  g_frx[BATCH * CHANNELS];
__device__ float  g_fry[BATCH * CHANNELS];
__device__ float  g_ph [BATCH * CHANNELS];
__device__ float  g_amp[BATCH * CHANNELS];

// fp16 trig tables, p (w or h) FASTEST: [b][c][p]  (contiguous K-chunk blocks)
__device__ __half g_SAt[BATCH * CHANNELS * GRID_HW];
__device__ __half g_CAt[BATCH * CHANNELS * GRID_HW];
__device__ __half g_SBt[BATCH * CHANNELS * GRID_HW];
__device__ __half g_CBt[BATCH * CHANNELS * GRID_HW];

// fp16 weight (1/sqrt(C) folded), row-major [o][c]
__device__ __half g_Wh[CHANNELS * CHANNELS];

// ---------------- PTX helpers -----------------------------------------------
__device__ __forceinline__ uint32_t smem_u32(const void* p) {
    uint32_t a;
    asm("{ .reg .u64 t; cvta.to.shared.u64 t, %1; cvt.u32.u64 %0, t; }"
        : "=r"(a) : "l"(p));
    return a;
}

__device__ __forceinline__ void ldsm4(uint32_t* r, uint32_t addr) {
    asm volatile("ldmatrix.sync.aligned.m8n8.x4.shared.b16 {%0,%1,%2,%3}, [%4];"
                 : "=r"(r[0]), "=r"(r[1]), "=r"(r[2]), "=r"(r[3]) : "r"(addr));
}
__device__ __forceinline__ void ldsm4t(uint32_t* r, uint32_t addr) {
    asm volatile("ldmatrix.sync.aligned.m8n8.x4.trans.shared.b16 {%0,%1,%2,%3}, [%4];"
                 : "=r"(r[0]), "=r"(r[1]), "=r"(r[2]), "=r"(r[3]) : "r"(addr));
}

__device__ __forceinline__ void mma16816(float* d, const uint32_t* a,
                                         const uint32_t* b) {
    asm volatile(
        "mma.sync.aligned.m16n8k16.row.col.f32.f16.f16.f32 "
        "{%0,%1,%2,%3}, {%4,%5,%6,%7}, {%8,%9}, {%0,%1,%2,%3};"
        : "+f"(d[0]), "+f"(d[1]), "+f"(d[2]), "+f"(d[3])
        : "r"(a[0]), "r"(a[1]), "r"(a[2]), "r"(a[3]), "r"(b[0]), "r"(b[1]));
}

__device__ __forceinline__ void cp16(uint32_t dst, const void* src) {
    asm volatile("cp.async.ca.shared.global [%0], [%1], 16;"
                 :: "r"(dst), "l"(src));
}
__device__ __forceinline__ void cp4(uint32_t dst, const void* src) {
    asm volatile("cp.async.ca.shared.global [%0], [%1], 4;"
                 :: "r"(dst), "l"(src));
}
#define CP_COMMIT() asm volatile("cp.async.commit_group;" ::: "memory")
#define CP_WAIT0()  asm volatile("cp.async.wait_group 0;"  ::: "memory")
#define CP_WAIT1()  asm volatile("cp.async.wait_group 1;"  ::: "memory")

// ---------------- stage 1: per-batch params ----------------------------------
__global__ void params_kernel(const float* __restrict__ w,
                              const float* __restrict__ affine_w,
                              const float* __restrict__ affine_b,
                              const float* __restrict__ freqs,
                              const float* __restrict__ phases) {
    __shared__ float t[BATCH][4];
    __shared__ float cs[BATCH], ss[BATCH], trx[BATCH], trY[BATCH];

    int tid = threadIdx.x;          // 128 threads
    int b = tid >> 2, j = tid & 3;

    float acc = 0.f;
    const float* wr = w + b * W_DIM;
    const float* ar = affine_w + j * W_DIM;
    #pragma unroll 4
    for (int k = 0; k < W_DIM; k++) acc += wr[k] * ar[k];
    t[b][j] = acc * GAIN + affine_b[j];
    __syncthreads();

    if (j == 0) {
        float t0 = t[b][0], t1 = t[b][1], t2 = t[b][2], t3 = t[b][3];
        float inv = rsqrtf(t0 * t0 + t1 * t1);
        float c = t0 * inv, s = t1 * inv, tx = t2 * inv, ty = t3 * inv;
        cs[b] = c; ss[b] = s;
        trx[b] = -c * tx + s * ty;
        trY[b] = -s * tx - c * ty;
    }
    __syncthreads();

    for (int idx = tid; idx < BATCH * CHANNELS; idx += 128) {
        int bb = idx >> 10, c = idx & (CHANNELS - 1);
        float f0 = freqs[c * 2], f1 = freqs[c * 2 + 1];
        float C = cs[bb], S = ss[bb];
        float frx = f0 * C + f1 * S;
        float fry = -f0 * S + f1 * C;
        float ph  = phases[c] + f0 * trx[bb] + f1 * trY[bb];
        float nrm = sqrtf(frx * frx + fry * fry);
        float amp = 1.0f - (nrm - 2.0f) * (1.0f / 30.0f);
        amp = fminf(fmaxf(amp, 0.0f), 1.0f);
        g_frx[idx] = frx; g_fry[idx] = fry; g_ph[idx] = ph; g_amp[idx] = amp;
    }
}

// ---------------- stage 1b: weight -> fp16 -----------------------------------
__global__ void wconv_kernel(const float* __restrict__ weight) {
    int idx = blockIdx.x * blockDim.x + threadIdx.x;
    for (int i = idx; i < CHANNELS * CHANNELS; i += gridDim.x * blockDim.x)
        g_Wh[i] = __float2half(weight[i] * WSCALE);
}

// ---------------- stage 2: fp16 trig tables (p-fastest) ----------------------
__global__ void tables_kernel() {
    int tid = threadIdx.x;                       // 256
    int c = blockIdx.x * 4 + (tid >> 6);
    int p = tid & 63;
    int b = blockIdx.y;
    int pi = b * CHANNELS + c;
    float g = ((2 * p + 1) * (1.0f / GRID_HW) - 1.0f) * 0.5f;
    float frx = g_frx[pi], fry = g_fry[pi];
    float ph = g_ph[pi], amp = g_amp[pi];
    float sa, ca, sb, cb;
    sincosf(TWO_PI * g * frx, &sa, &ca);
    sincosf(TWO_PI * (g * fry + ph), &sb, &cb);
    int o = pi * GRID_HW + p;
    g_SAt[o] = __float2half(amp * sa);
    g_CAt[o] = __float2half(amp * ca);
    g_SBt[o] = __float2half(sb);
    g_CBt[o] = __float2half(cb);
}

// ---------------- stage 3: fused mma.sync GEMM -------------------------------
// CTA tile: M=256 (o) x N=128 (px), K=1024 in 32 iters of BK=32.
// Software pipeline: tables staged 2 ahead (3 bufs), A staged 1 ahead (3 bufs),
// genB(k+1) interleaved with MMA(k); single __syncthreads per iteration.
#define BK       32
#define NKIT     (CHANNELS / BK)
#define ASTRIDE  40      // halves
#define BSTRIDE  136     // halves
#define TSTRIDE  72      // halves

#define ABUF     10240   // halves per A buffer (256*40)
#define BBUF     4352    // halves per B buffer (32*136)
#define T_CA     2304
#define T_SB     4608
#define T_CB     4672
#define TBUF     4736    // halves per table buffer

#define OFF_A    0                          // 3 * 10240 = 30720
#define OFF_B    30720                      // 2 * 4352  = 8704
#define OFF_T    39424                      // 3 * 4736  = 14208
#define SMEM_HALVES (39424 + 3 * 4736)      // 53632
#define SMEM_BYTES  (SMEM_HALVES * 2)       // 107264

__global__ void __launch_bounds__(256, 1)
gemm_mma(float* __restrict__ out) {
    extern __shared__ __half sh[];
    int tid = threadIdx.x;
    int ot = blockIdx.x;   // 4
    int pt = blockIdx.y;   // 32
    int b  = blockIdx.z;   // 32

    uint32_t sAu = smem_u32(sh + OFF_A);
    uint32_t sBu = smem_u32(sh + OFF_B);
    uint32_t sTu = smem_u32(sh + OFF_T);
    int h0 = pt * 2;

    // ---- staging maps -------------------------------------------------------
    int arow = tid >> 2, aseg = tid & 3;                 // A: 4 lanes/row
    const __half* wsrc0 = g_Wh + (size_t)(ot * 256 + arow) * CHANNELS + aseg * 8;
    int trow = tid >> 3, tseg = tid & 7;                 // tables: 8 lanes/row

    auto stage_A = [&](int k, int buf3) {
        uint32_t ad = sAu + (uint32_t)(buf3 * ABUF + arow * ASTRIDE + aseg * 8) * 2;
        const __half* ws = wsrc0 + k * BK;
        #pragma unroll
        for (int j = 0; j < 4; j++)
            cp16(ad + (uint32_t)(j * 64 * ASTRIDE) * 2, ws + (size_t)j * 64 * CHANNELS);
    };
    auto stage_T = [&](int k, int buf3) {
        int ck = k * BK;
        const __half* sasrc = g_SAt + ((size_t)(b * CHANNELS + ck + trow) << 6) + tseg * 8;
        const __half* casrc = g_CAt + ((size_t)(b * CHANNELS + ck + trow) << 6) + tseg * 8;
        uint32_t td = sTu + (uint32_t)(buf3 * TBUF + trow * TSTRIDE + tseg * 8) * 2;
        cp16(td, sasrc);
        cp16(td + T_CA * 2, casrc);
        if (tid < 32) {
            const __half* s = g_SBt + ((size_t)(b * CHANNELS + ck + tid) << 6) + h0;
            cp4(sTu + (uint32_t)(buf3 * TBUF + T_SB + tid * 2) * 2, s);
        } else if (tid < 64) {
            int c = tid - 32;
            const __half* s = g_CBt + ((size_t)(b * CHANNELS + ck + c) << 6) + h0;
            cp4(sTu + (uint32_t)(buf3 * TBUF + T_CB + c * 2) * 2, s);
        }
    };

    // ---- genB map -----------------------------------------------------------
    int gc = tid >> 3;            // c row 0..31
    int gj = tid & 7;             // px-16 group
    int gpx = gj * 16;
    int gh = gpx >> 6;            // 0..1
    int gw = gpx & 63;

    // ---- mma geometry -------------------------------------------------------
    int wid = tid >> 5, lane = tid & 31;
    int m0 = (wid >> 1) * 64;     // 0..192
    int n0 = (wid & 1) * 64;      // 0 / 64
    uint32_t aAddr0 = sAu + (uint32_t)((m0 + (lane & 15)) * ASTRIDE + (lane >> 4) * 8) * 2;
    uint32_t bAddr0 = sBu + (uint32_t)((lane & 15) * BSTRIDE + n0 + (lane >> 4) * 8) * 2;

    float acc[4][8][4];
    #pragma unroll
    for (int i = 0; i < 4; i++)
        #pragma unroll
        for (int j = 0; j < 8; j++)
            #pragma unroll
            for (int q = 0; q < 4; q++) acc[i][j][q] = 0.f;

    // ---- prologue: stage T0, T1, A0; genB(0) --------------------------------
    stage_A(0, 0);
    stage_T(0, 0);
    stage_T(1, 1);
    CP_COMMIT();
    CP_WAIT0();
    __syncthreads();
    {   // genB(0) -> B buf 0, reads T buf 0
        const __half* T = sh + OFF_T;
        uint4 xsa0 = *(const uint4*)(T + gc * TSTRIDE + gw);
        uint4 xsa1 = *(const uint4*)(T + gc * TSTRIDE + gw + 8);
        uint4 xca0 = *(const uint4*)(T + T_CA + gc * TSTRIDE + gw);
        uint4 xca1 = *(const uint4*)(T + T_CA + gc * TSTRIDE + gw + 8);
        __half2 sb2 = __half2half2(T[T_SB + gc * 2 + gh]);
        __half2 cb2 = __half2half2(T[T_CB + gc * 2 + gh]);
        uint4 o0, o1;
        #pragma unroll
        for (int j = 0; j < 4; j++) {
            ((__half2*)&o0)[j] = __hfma2(((const __half2*)&xsa0)[j], cb2,
                                 __hmul2(((const __half2*)&xca0)[j], sb2));
            ((__half2*)&o1)[j] = __hfma2(((const __half2*)&xsa1)[j], cb2,
                                 __hmul2(((const __half2*)&xca1)[j], sb2));
        }
        __half* d = sh + OFF_B + gc * BSTRIDE + gpx;
        *(uint4*)d = o0;
        *(uint4*)(d + 8) = o1;
    }

    // ---- main loop: 1 barrier per iter, genB(k+1) overlapped with MMA(k) ----
    int a_cur = 0, t_nxt = 1, b_cur = 0;
    #pragma unroll 1
    for (int k = 0; k < NKIT; k++) {
        int a_nxt = a_cur + 1; if (a_nxt == 3) a_nxt = 0;
        int t_n2  = t_nxt + 1; if (t_n2 == 3) t_n2 = 0;

        // stage ahead: A(k+1), T(k+2)
        if (k + 1 < NKIT) stage_A(k + 1, a_nxt);
        if (k + 2 < NKIT) stage_T(k + 2, t_n2);
        CP_COMMIT();
        CP_WAIT1();            // group from iter k-1 (A(k), T(k+1)) complete
        __syncthreads();       // genB(k) from prev iter visible; buffers safe

        bool do_gen = (k + 1 < NKIT);

        // -- genB(k+1) input loads (issue early; long-latency LDS) ------------
        uint4 xsa0, xsa1, xca0, xca1;
        __half2 sb2, cb2;
        if (do_gen) {
            const __half* T = sh + OFF_T + t_nxt * TBUF;
            xsa0 = *(const uint4*)(T + gc * TSTRIDE + gw);
            xsa1 = *(const uint4*)(T + gc * TSTRIDE + gw + 8);
            xca0 = *(const uint4*)(T + T_CA + gc * TSTRIDE + gw);
            xca1 = *(const uint4*)(T + T_CA + gc * TSTRIDE + gw + 8);
            sb2 = __half2half2(T[T_SB + gc * 2 + gh]);
            cb2 = __half2half2(T[T_CB + gc * 2 + gh]);
        }

        // -- MMA(k) -----------------------------------------------------------
        uint32_t aA = aAddr0 + (uint32_t)(a_cur * ABUF) * 2;
        uint32_t bA = bAddr0 + (uint32_t)(b_cur * BBUF) * 2;
        #pragma unroll
        for (int ks = 0; ks < 2; ks++) {
            uint32_t af[4][4], bf[4][4];
            #pragma unroll
            for (int im = 0; im < 4; im++)
                ldsm4(af[im], aA + (uint32_t)(im * 16 * ASTRIDE) * 2 + ks * 32);
            #pragma unroll
            for (int in = 0; in < 4; in++)
                ldsm4t(bf[in], bA + (uint32_t)(ks * 16 * BSTRIDE) * 2 + in * 32);
            #pragma unroll
            for (int im = 0; im < 4; im++)
                #pragma unroll
                for (int in = 0; in < 4; in++) {
                    mma16816(acc[im][2 * in],     af[im], &bf[in][0]);
                    mma16816(acc[im][2 * in + 1], af[im], &bf[in][2]);
                }
        }

        // -- genB(k+1) compute + store (overlaps MMA issue window) ------------
        if (do_gen) {
            uint4 o0, o1;
            #pragma unroll
            for (int j = 0; j < 4; j++) {
                ((__half2*)&o0)[j] = __hfma2(((const __half2*)&xsa0)[j], cb2,
                                     __hmul2(((const __half2*)&xca0)[j], sb2));
                ((__half2*)&o1)[j] = __hfma2(((const __half2*)&xsa1)[j], cb2,
                                     __hmul2(((const __half2*)&xca1)[j], sb2));
            }
            __half* d = sh + OFF_B + (b_cur ^ 1) * BBUF + gc * BSTRIDE + gpx;
            *(uint4*)d = o0;
            *(uint4*)(d + 8) = o1;
        }

        a_cur = a_nxt;
        t_nxt = t_n2;
        b_cur ^= 1;
    }

    // ---- epilogue: direct STG, 32B-sector coalesced -------------------------
    #pragma unroll
    for (int im = 0; im < 4; im++) {
        int o = ot * 256 + m0 + im * 16 + (lane >> 2);
        float* p = out + ((size_t)(b * CHANNELS + o)) * HW
                       + (size_t)pt * 128 + n0 + 2 * (lane & 3);
        #pragma unroll
        for (int inf = 0; inf < 8; inf++) {
            float2 vlo = make_float2(acc[im][inf][0], acc[im][inf][1]);
            float2 vhi = make_float2(acc[im][inf][2], acc[im][inf][3]);
            *(float2*)(p + inf * 8)          = vlo;   // row o
            *(float2*)(p + inf * 8 + 8 * HW) = vhi;   // row o+8
        }
    }
}

// ---------------- launch ------------------------------------------------------
extern "C" void kernel_launch(void* const* d_in, const int* in_sizes, int n_in,
                              void* d_out, int out_size) {
    const float* w        = (const float*)d_in[0];
    const float* affine_w = (const float*)d_in[1];
    const float* affine_b = (const float*)d_in[2];
    const float* freqs    = (const float*)d_in[3];
    const float* phases   = (const float*)d_in[4];
    const float* weight   = (const float*)d_in[5];
    float* out = (float*)d_out;

    cudaFuncSetAttribute(gemm_mma, cudaFuncAttributeMaxDynamicSharedMemorySize,
                         SMEM_BYTES);

    params_kernel<<<1, 128>>>(w, affine_w, affine_b, freqs, phases);
    wconv_kernel<<<512, 256>>>(weight);
    tables_kernel<<<dim3(CHANNELS / 4, BATCH), 256>>>();
    gemm_mma<<<dim3(4, 32, BATCH), 256, SMEM_BYTES>>>(out);
}